// round 8
// baseline (speedup 1.0000x reference)
#include <cuda_runtime.h>
#include <cuda_bf16.h>
#include <math.h>
#include <stdint.h>

#define DMODEL 1024
#define DFF 4096
#define SEQ 2048
#define NTOK 4096
#define LN_EPS 1e-5f
typedef __nv_bfloat16 bf16;
typedef unsigned long long ull;

// ---------------- device-global scratch ----------------
__device__ bf16 g_wqt_h[1u<<20], g_wqt_l[1u<<20];   // [N,K] K-major (wq pre-scaled 0.125)
__device__ bf16 g_wkt_h[1u<<20], g_wkt_l[1u<<20];
__device__ bf16 g_wvt_h[1u<<20], g_wvt_l[1u<<20];
__device__ bf16 g_wot_h[1u<<20], g_wot_l[1u<<20];
__device__ bf16 g_w1t_h[1u<<22], g_w1t_l[1u<<22];
__device__ bf16 g_w2t_h[1u<<22], g_w2t_l[1u<<22];
__device__ bf16 g_xn_h [1u<<22], g_xn_l [1u<<22];
__device__ bf16 g_q_h  [1u<<22], g_q_l  [1u<<22];
__device__ bf16 g_k_h  [1u<<22], g_k_l  [1u<<22];
__device__ bf16 g_vt_h [1u<<22], g_vt_l [1u<<22];   // [1024 dk, 4096 tok]
__device__ bf16 g_ctx_h[1u<<22], g_ctx_l[1u<<22];
__device__ bf16 g_ffh_h[1u<<24], g_ffh_l[1u<<24];   // [4096,4096]
__device__ float g_x1[1u<<22];
__device__ float g_xn_f [1u<<22];                   // fp32 copies for SIMT tiles
__device__ float g_ctx_f[1u<<22];
__device__ float g_ffh_f[1u<<24];

// ---------------- helpers ----------------
__device__ __forceinline__ void mma16816(float* d, const uint32_t* a, const uint32_t* b) {
    asm volatile(
        "mma.sync.aligned.m16n8k16.row.col.f32.bf16.bf16.f32 "
        "{%0,%1,%2,%3}, {%4,%5,%6,%7}, {%8,%9}, {%0,%1,%2,%3};"
        : "+f"(d[0]), "+f"(d[1]), "+f"(d[2]), "+f"(d[3])
        : "r"(a[0]), "r"(a[1]), "r"(a[2]), "r"(a[3]), "r"(b[0]), "r"(b[1]));
}
__device__ __forceinline__ uint16_t bfbits(bf16 v) { return __bfloat16_as_ushort(v); }
__device__ __forceinline__ void split(float f, bf16* h, bf16* l) {
    bf16 hh = __float2bfloat16(f);
    *h = hh; *l = __float2bfloat16(f - __bfloat162float(hh));
}
__device__ __forceinline__ ull pk2(float x) {
    ull r; asm("mov.b64 %0, {%1,%1};" : "=l"(r) : "f"(x)); return r;
}
__device__ __forceinline__ void fma2(ull& d, ull a, ull b) {
    asm("fma.rn.f32x2 %0, %1, %2, %0;" : "+l"(d) : "l"(a), "l"(b));
}
__device__ __forceinline__ float2 unpk(ull v) {
    float2 r; asm("mov.b64 {%0,%1}, %2;" : "=f"(r.x), "=f"(r.y) : "l"(v)); return r;
}
__device__ __forceinline__ float warpSum(float v) {
    #pragma unroll
    for (int o = 16; o > 0; o >>= 1) v += __shfl_down_sync(0xffffffffu, v, o);
    return v;
}
__device__ __forceinline__ float blockSum(float v) {
    __shared__ float sh[8];
    int l = threadIdx.x & 31, w = threadIdx.x >> 5;
    v = warpSum(v);
    if (l == 0) sh[w] = v;
    __syncthreads();
    if (w == 0) { float t = (l < 8) ? sh[l] : 0.f; t = warpSum(t); if (l == 0) sh[0] = t; }
    __syncthreads();
    float r = sh[0]; __syncthreads();
    return r;
}

// ---------------- weight prep ----------------
__global__ void __launch_bounds__(256) k_prep(const float* __restrict__ w, int id, int K, int N)
{
    bf16 *th, *tl;
    float scale = 1.0f;
    switch (id) {
        case 0: th = g_wqt_h; tl = g_wqt_l; scale = 0.125f; break;
        case 1: th = g_wkt_h; tl = g_wkt_l; break;
        case 2: th = g_wvt_h; tl = g_wvt_l; break;
        case 3: th = g_wot_h; tl = g_wot_l; break;
        case 4: th = g_w1t_h; tl = g_w1t_l; break;
        default: th = g_w2t_h; tl = g_w2t_l; break;
    }
    __shared__ float ts[32][33];
    int tx = threadIdx.x & 31, ty = threadIdx.x >> 5;
    int n0 = blockIdx.x * 32, k0 = blockIdx.y * 32;
    #pragma unroll
    for (int i = 0; i < 4; i++)
        ts[ty + 8*i][tx] = w[(size_t)(k0 + ty + 8*i) * N + n0 + tx];
    __syncthreads();
    #pragma unroll
    for (int i = 0; i < 4; i++) {
        int n = n0 + ty + 8*i, k = k0 + tx;
        split(ts[tx][ty + 8*i] * scale, &th[(size_t)n * K + k], &tl[(size_t)n * K + k]);
    }
}

// ---------------- LayerNorm -> bf16 hi/lo + fp32 ----------------
__global__ void __launch_bounds__(256) k_ln(const float* __restrict__ xin, int use_x1,
                                            const float* __restrict__ ap,
                                            const float* __restrict__ bp)
{
    const float* src = use_x1 ? g_x1 : xin;
    int row = blockIdx.x, t = threadIdx.x;
    const float* xr = src + (size_t)row * DMODEL;
    float v[4], s = 0.f, sq = 0.f;
    #pragma unroll
    for (int i = 0; i < 4; i++) { v[i] = xr[t + 256*i]; s += v[i]; sq += v[i]*v[i]; }
    s = blockSum(s); sq = blockSum(sq);
    float mean = s * (1.0f / DMODEL);
    float var = fmaxf((sq - (float)DMODEL * mean * mean) * (1.0f / (DMODEL - 1)), 0.f);
    float sc = ap[0] / (sqrtf(var) + LN_EPS);
    float bi = bp[0];
    #pragma unroll
    for (int i = 0; i < 4; i++) {
        size_t o = (size_t)row * DMODEL + t + 256*i;
        float y = (v[i] - mean) * sc + bi;
        g_xn_f[o] = y;
        split(y, &g_xn_h[o], &g_xn_l[o]);
    }
}

// ---------------------------------------------------------------------------
// Fused flash attention (unchanged logic from R7; adds fp32 ctx output)
// ---------------------------------------------------------------------------
__global__ void __launch_bounds__(256) kt_attn(const int* __restrict__ mask)
{
    const int z = blockIdx.y, b = z >> 4, h = z & 15;
    const int q0 = blockIdx.x * 128;
    const int tid = threadIdx.x, wid = tid >> 5, lane = tid & 31;
    const int g = lane >> 2, t4 = lane & 3;

    __shared__ __align__(16) uint16_t sKh[64*72], sKl[64*72];
    __shared__ __align__(16) uint16_t sVh[64*72], sVl[64*72];
    __shared__ int s_mask[SEQ];

    for (int i = tid; i < SEQ/4; i += 256)
        *(int4*)&s_mask[i*4] = *(const int4*)&mask[b*SEQ + i*4];

    uint32_t qh[4][4], ql[4][4];
    {
        const uint32_t* Q32h = (const uint32_t*)g_q_h;
        const uint32_t* Q32l = (const uint32_t*)g_q_l;
        size_t r0 = ((size_t)(b*SEQ + q0 + wid*16 + g)) * 512 + h*32;
        size_t r8 = r0 + 8*512;
        #pragma unroll
        for (int s = 0; s < 4; s++) {
            qh[s][0] = Q32h[r0 + s*8 + t4];
            qh[s][1] = Q32h[r8 + s*8 + t4];
            qh[s][2] = Q32h[r0 + s*8 + 4 + t4];
            qh[s][3] = Q32h[r8 + s*8 + 4 + t4];
            ql[s][0] = Q32l[r0 + s*8 + t4];
            ql[s][1] = Q32l[r8 + s*8 + t4];
            ql[s][2] = Q32l[r0 + s*8 + 4 + t4];
            ql[s][3] = Q32l[r8 + s*8 + 4 + t4];
        }
    }

    float O[8][4];
    #pragma unroll
    for (int i = 0; i < 8; i++)
        #pragma unroll
        for (int j = 0; j < 4; j++) O[i][j] = 0.f;
    float m0 = -INFINITY, m1 = -INFINITY, l0 = 0.f, l1 = 0.f;

    const int krow = tid >> 2, kcb = (tid & 3) * 16;
    const uint32_t* K32h = (const uint32_t*)sKh;
    const uint32_t* K32l = (const uint32_t*)sKl;
    const uint32_t* V32h = (const uint32_t*)sVh;
    const uint32_t* V32l = (const uint32_t*)sVl;

    for (int kt = 0; kt < SEQ/64; kt++) {
        __syncthreads();
        {
            size_t gk = ((size_t)(b*SEQ + kt*64 + krow)) * 1024 + h*64 + kcb;
            *(uint4*)&sKh[krow*72 + kcb]     = *(const uint4*)&g_k_h[gk];
            *(uint4*)&sKh[krow*72 + kcb + 8] = *(const uint4*)&g_k_h[gk + 8];
            *(uint4*)&sKl[krow*72 + kcb]     = *(const uint4*)&g_k_l[gk];
            *(uint4*)&sKl[krow*72 + kcb + 8] = *(const uint4*)&g_k_l[gk + 8];
            size_t gv = ((size_t)(h*64 + krow)) * 4096 + b*SEQ + kt*64 + kcb;
            *(uint4*)&sVh[krow*72 + kcb]     = *(const uint4*)&g_vt_h[gv];
            *(uint4*)&sVh[krow*72 + kcb + 8] = *(const uint4*)&g_vt_h[gv + 8];
            *(uint4*)&sVl[krow*72 + kcb]     = *(const uint4*)&g_vt_l[gv];
            *(uint4*)&sVl[krow*72 + kcb + 8] = *(const uint4*)&g_vt_l[gv + 8];
        }
        __syncthreads();

        float s[8][4];
        #pragma unroll
        for (int nt = 0; nt < 8; nt++) {
            s[nt][0] = s[nt][1] = s[nt][2] = s[nt][3] = 0.f;
            const int nr = (nt*8 + g) * 36;
            #pragma unroll
            for (int ks = 0; ks < 4; ks++) {
                uint32_t bh[2] = { K32h[nr + ks*8 + t4], K32h[nr + ks*8 + 4 + t4] };
                uint32_t bl[2] = { K32l[nr + ks*8 + t4], K32l[nr + ks*8 + 4 + t4] };
                mma16816(s[nt], qh[ks], bh);
                mma16816(s[nt], qh[ks], bl);
                mma16816(s[nt], ql[ks], bh);
            }
        }
        #pragma unroll
        for (int nt = 0; nt < 8; nt++) {
            const int c = kt*64 + nt*8 + 2*t4;
            if (s_mask[c]   == 0) { s[nt][0] = -1e9f; s[nt][2] = -1e9f; }
            if (s_mask[c+1] == 0) { s[nt][1] = -1e9f; s[nt][3] = -1e9f; }
        }
        float mx0 = -INFINITY, mx1 = -INFINITY;
        #pragma unroll
        for (int nt = 0; nt < 8; nt++) {
            mx0 = fmaxf(mx0, fmaxf(s[nt][0], s[nt][1]));
            mx1 = fmaxf(mx1, fmaxf(s[nt][2], s[nt][3]));
        }
        mx0 = fmaxf(mx0, __shfl_xor_sync(0xffffffffu, mx0, 1));
        mx0 = fmaxf(mx0, __shfl_xor_sync(0xffffffffu, mx0, 2));
        mx1 = fmaxf(mx1, __shfl_xor_sync(0xffffffffu, mx1, 1));
        mx1 = fmaxf(mx1, __shfl_xor_sync(0xffffffffu, mx1, 2));
        float nm0 = fmaxf(m0, mx0), nm1 = fmaxf(m1, mx1);
        float a0 = __expf(m0 - nm0), a1 = __expf(m1 - nm1);
        m0 = nm0; m1 = nm1;
        float ps0 = 0.f, ps1 = 0.f;
        #pragma unroll
        for (int nt = 0; nt < 8; nt++) {
            s[nt][0] = __expf(s[nt][0] - nm0);
            s[nt][1] = __expf(s[nt][1] - nm0);
            s[nt][2] = __expf(s[nt][2] - nm1);
            s[nt][3] = __expf(s[nt][3] - nm1);
            ps0 += s[nt][0] + s[nt][1];
            ps1 += s[nt][2] + s[nt][3];
        }
        ps0 += __shfl_xor_sync(0xffffffffu, ps0, 1);
        ps0 += __shfl_xor_sync(0xffffffffu, ps0, 2);
        ps1 += __shfl_xor_sync(0xffffffffu, ps1, 1);
        ps1 += __shfl_xor_sync(0xffffffffu, ps1, 2);
        l0 = l0 * a0 + ps0;
        l1 = l1 * a1 + ps1;
        #pragma unroll
        for (int nt = 0; nt < 8; nt++) {
            O[nt][0] *= a0; O[nt][1] *= a0;
            O[nt][2] *= a1; O[nt][3] *= a1;
        }
        uint32_t pH[4][4], pL[4][4];
        #pragma unroll
        for (int ks = 0; ks < 4; ks++) {
            #pragma unroll
            for (int half = 0; half < 2; half++) {
                const int nt = 2*ks + half;
                bf16 h0 = __float2bfloat16(s[nt][0]);
                bf16 h1 = __float2bfloat16(s[nt][1]);
                bf16 h2 = __float2bfloat16(s[nt][2]);
                bf16 h3 = __float2bfloat16(s[nt][3]);
                pH[ks][2*half]   = (uint32_t)bfbits(h0) | ((uint32_t)bfbits(h1) << 16);
                pH[ks][2*half+1] = (uint32_t)bfbits(h2) | ((uint32_t)bfbits(h3) << 16);
                bf16 e0 = __float2bfloat16(s[nt][0] - __bfloat162float(h0));
                bf16 e1 = __float2bfloat16(s[nt][1] - __bfloat162float(h1));
                bf16 e2 = __float2bfloat16(s[nt][2] - __bfloat162float(h2));
                bf16 e3 = __float2bfloat16(s[nt][3] - __bfloat162float(h3));
                pL[ks][2*half]   = (uint32_t)bfbits(e0) | ((uint32_t)bfbits(e1) << 16);
                pL[ks][2*half+1] = (uint32_t)bfbits(e2) | ((uint32_t)bfbits(e3) << 16);
            }
        }
        #pragma unroll
        for (int nt = 0; nt < 8; nt++) {
            const int nr = (nt*8 + g) * 36;
            #pragma unroll
            for (int ks = 0; ks < 4; ks++) {
                uint32_t bh[2] = { V32h[nr + ks*8 + t4], V32h[nr + ks*8 + 4 + t4] };
                uint32_t bl[2] = { V32l[nr + ks*8 + t4], V32l[nr + ks*8 + 4 + t4] };
                mma16816(O[nt], pH[ks], bh);
                mma16816(O[nt], pH[ks], bl);
                mma16816(O[nt], pL[ks], bh);
            }
        }
    }

    const float il0 = 1.0f / l0, il1 = 1.0f / l1;
    const size_t row0 = (size_t)(b*SEQ + q0 + wid*16 + g);
    const size_t row8 = row0 + 8;
    #pragma unroll
    for (int nt = 0; nt < 8; nt++) {
        const int col = h*64 + nt*8 + 2*t4;
        float f0 = O[nt][0] * il0, f1 = O[nt][1] * il0;
        float f2 = O[nt][2] * il1, f3 = O[nt][3] * il1;
        bf16 h0, l0b, h1, l1b;
        split(f0, &h0, &l0b); split(f1, &h1, &l1b);
        *(uint32_t*)(g_ctx_h + row0*1024 + col) =
            (uint32_t)bfbits(h0) | ((uint32_t)bfbits(h1) << 16);
        *(uint32_t*)(g_ctx_l + row0*1024 + col) =
            (uint32_t)bfbits(l0b) | ((uint32_t)bfbits(l1b) << 16);
        float2 fa; fa.x = f0; fa.y = f1;
        *(float2*)(g_ctx_f + row0*1024 + col) = fa;
        split(f2, &h0, &l0b); split(f3, &h1, &l1b);
        *(uint32_t*)(g_ctx_h + row8*1024 + col) =
            (uint32_t)bfbits(h0) | ((uint32_t)bfbits(h1) << 16);
        *(uint32_t*)(g_ctx_l + row8*1024 + col) =
            (uint32_t)bfbits(l0b) | ((uint32_t)bfbits(l1b) << 16);
        float2 fb; fb.x = f2; fb.y = f3;
        *(float2*)(g_ctx_f + row8*1024 + col) = fb;
    }
}

// ---------------------------------------------------------------------------
// HMMA GEMM core (R7 tcore, now pool-based). 128(M) x 128(N), K-chunks of 32.
// EPI: 0 pair-out | 2 pair-out transposed | 4 fp32+resid | 5 fp32+bias+resid
//      6 bias+relu pair-out + fp32 (writes g_ffh_f)
// ---------------------------------------------------------------------------
template<int EPI>
__device__ __forceinline__ void tcore(
    uint8_t* pool,
    const bf16* __restrict__ Ah, const bf16* __restrict__ Al, int lda,
    const bf16* __restrict__ Bh, const bf16* __restrict__ Bl, int ldb,
    int K, int bm, int bn,
    float* __restrict__ Cf, int ldc,
    bf16* __restrict__ Oh, bf16* __restrict__ Ol, int ldo,
    const float* __restrict__ bias, const float* __restrict__ resid)
{
    constexpr int RS = 40;
    uint16_t* sAh = (uint16_t*)pool;        // 128*40
    uint16_t* sAl = sAh + 128*RS;
    uint16_t* sBh = sAl + 128*RS;
    uint16_t* sBl = sBh + 128*RS;

    const int tid = threadIdx.x, wid = tid >> 5, lane = tid & 31;
    const int wm = wid & 3, wn = wid >> 2;
    const int g = lane >> 2, t4 = lane & 3;

    const int ar = tid >> 1, akq = (tid & 1) * 16;

    float acc[2][8][4];
    #pragma unroll
    for (int i = 0; i < 2; i++)
        #pragma unroll
        for (int j = 0; j < 8; j++)
            #pragma unroll
            for (int e = 0; e < 4; e++) acc[i][j][e] = 0.f;

    uint4 pAh[2], pAl[2], pBh[2], pBl[2];
    auto prefetch = [&](int k0) {
        const bf16* a_h = Ah + (size_t)(bm + ar) * lda + k0 + akq;
        const bf16* a_l = Al + (size_t)(bm + ar) * lda + k0 + akq;
        pAh[0] = *(const uint4*)a_h;       pAh[1] = *(const uint4*)(a_h + 8);
        pAl[0] = *(const uint4*)a_l;       pAl[1] = *(const uint4*)(a_l + 8);
        const bf16* b_h = Bh + (size_t)(bn + ar) * ldb + k0 + akq;
        const bf16* b_l = Bl + (size_t)(bn + ar) * ldb + k0 + akq;
        pBh[0] = *(const uint4*)b_h;       pBh[1] = *(const uint4*)(b_h + 8);
        pBl[0] = *(const uint4*)b_l;       pBl[1] = *(const uint4*)(b_l + 8);
    };
    auto store_smem = [&]() {
        *(uint4*)&sAh[ar*RS + akq]     = pAh[0];
        *(uint4*)&sAh[ar*RS + akq + 8] = pAh[1];
        *(uint4*)&sAl[ar*RS + akq]     = pAl[0];
        *(uint4*)&sAl[ar*RS + akq + 8] = pAl[1];
        *(uint4*)&sBh[ar*RS + akq]     = pBh[0];
        *(uint4*)&sBh[ar*RS + akq + 8] = pBh[1];
        *(uint4*)&sBl[ar*RS + akq]     = pBl[0];
        *(uint4*)&sBl[ar*RS + akq + 8] = pBl[1];
    };

    const uint32_t* A32h = (const uint32_t*)sAh;
    const uint32_t* A32l = (const uint32_t*)sAl;
    const uint32_t* B32h = (const uint32_t*)sBh;
    const uint32_t* B32l = (const uint32_t*)sBl;
    const int RS2 = RS / 2;

    const int nch = K >> 5;
    prefetch(0);
    for (int c = 0; c < nch; c++) {
        __syncthreads();
        store_smem();
        __syncthreads();
        if (c + 1 < nch) prefetch((c + 1) << 5);

        #pragma unroll
        for (int kh = 0; kh < 2; kh++) {
            const int ko = kh * 8;
            uint32_t aH[2][4], aL[2][4];
            #pragma unroll
            for (int mt = 0; mt < 2; mt++) {
                const int r = wm*32 + mt*16 + g;
                aH[mt][0] = A32h[r*RS2 + ko + t4];
                aH[mt][1] = A32h[(r+8)*RS2 + ko + t4];
                aH[mt][2] = A32h[r*RS2 + ko + 4 + t4];
                aH[mt][3] = A32h[(r+8)*RS2 + ko + 4 + t4];
                aL[mt][0] = A32l[r*RS2 + ko + t4];
                aL[mt][1] = A32l[(r+8)*RS2 + ko + t4];
                aL[mt][2] = A32l[r*RS2 + ko + 4 + t4];
                aL[mt][3] = A32l[(r+8)*RS2 + ko + 4 + t4];
            }
            #pragma unroll
            for (int nt = 0; nt < 8; nt++) {
                const int nr = wn*64 + nt*8 + g;
                uint32_t bH[2], bL[2];
                bH[0] = B32h[nr*RS2 + ko + t4];
                bH[1] = B32h[nr*RS2 + ko + 4 + t4];
                bL[0] = B32l[nr*RS2 + ko + t4];
                bL[1] = B32l[nr*RS2 + ko + 4 + t4];
                #pragma unroll
                for (int mt = 0; mt < 2; mt++) {
                    mma16816(acc[mt][nt], aH[mt], bH);
                    mma16816(acc[mt][nt], aH[mt], bL);
                    mma16816(acc[mt][nt], aL[mt], bH);
                }
            }
        }
    }

    auto wr = [&](int row, int col, float v0, float v1) {
        if (EPI == 0) {
            bf16 h0, l0, h1, l1;
            split(v0, &h0, &l0); split(v1, &h1, &l1);
            *(uint32_t*)(Oh + (size_t)row * ldo + col) =
                (uint32_t)bfbits(h0) | ((uint32_t)bfbits(h1) << 16);
            *(uint32_t*)(Ol + (size_t)row * ldo + col) =
                (uint32_t)bfbits(l0) | ((uint32_t)bfbits(l1) << 16);
        } else if (EPI == 2) {
            bf16 h0, l0, h1, l1;
            split(v0, &h0, &l0); split(v1, &h1, &l1);
            Oh[(size_t)col * ldo + row] = h0;
            Ol[(size_t)col * ldo + row] = l0;
            Oh[(size_t)(col + 1) * ldo + row] = h1;
            Ol[(size_t)(col + 1) * ldo + row] = l1;
        } else if (EPI == 6) {
            float f0 = fmaxf(v0 + bias[col], 0.f);
            float f1 = fmaxf(v1 + bias[col + 1], 0.f);
            bf16 h0, l0, h1, l1;
            split(f0, &h0, &l0); split(f1, &h1, &l1);
            *(uint32_t*)(Oh + (size_t)row * ldo + col) =
                (uint32_t)bfbits(h0) | ((uint32_t)bfbits(h1) << 16);
            *(uint32_t*)(Ol + (size_t)row * ldo + col) =
                (uint32_t)bfbits(l0) | ((uint32_t)bfbits(l1) << 16);
            float2 ff; ff.x = f0; ff.y = f1;
            *(float2*)(g_ffh_f + (size_t)row * 4096 + col) = ff;
        } else {
            const float* rr = resid + (size_t)row * ldc + col;
            float2 o;
            o.x = v0 + rr[0]; o.y = v1 + rr[1];
            if (EPI == 5) { o.x += bias[col]; o.y += bias[col + 1]; }
            *(float2*)(Cf + (size_t)row * ldc + col) = o;
        }
    };
    #pragma unroll
    for (int mt = 0; mt < 2; mt++) {
        #pragma unroll
        for (int nt = 0; nt < 8; nt++) {
            const int row = bm + wm*32 + mt*16 + g;
            const int col = bn + wn*64 + nt*8 + 2*t4;
            wr(row,     col, acc[mt][nt][0], acc[mt][nt][1]);
            wr(row + 8, col, acc[mt][nt][2], acc[mt][nt][3]);
        }
    }
}

// ---------------------------------------------------------------------------
// SIMT FFMA2 fp32 GEMM core (R2, proven): 128x128 tile, BK=8, double-buffered.
// A [M,K] fp32 row-major; B [K,N] fp32 row-major (ORIGINAL weights).
// EPI matches tcore codes; oscale applied before pair-split (EPI 0).
// ---------------------------------------------------------------------------
template<int EPI>
__device__ __forceinline__ void score(
    uint8_t* pool,
    const float* __restrict__ A, const float* __restrict__ B,
    int K, int lda, int ldb, int bm, int bn,
    const float* __restrict__ bias, const float* __restrict__ resid,
    float* __restrict__ Cf, int ldc,
    bf16* __restrict__ Oh, bf16* __restrict__ Ol, int ldo, float oscale)
{
    float* As = (float*)pool;          // 2 * 8*132 floats
    float* Bs = As + 2*8*132;          // 2 * 8*128 floats
    const int tid = threadIdx.x;
    const int arow = tid >> 1, ac = (tid & 1) * 4;
    const int brow = tid >> 5, bc4 = (tid & 31) * 4;
    const float* Ap = A + (size_t)(bm + arow) * lda + ac;
    const float* Bp = B + (size_t)brow * ldb + bn + bc4;
    const int tx = tid & 15, ty = tid >> 4;
    const int r0 = ty * 4, r1 = 64 + ty * 4;
    const int c0 = tx * 4, c1 = 64 + tx * 4;

    ull acc[4][8];
    #pragma unroll
    for (int i = 0; i < 4; i++)
        #pragma unroll
        for (int j = 0; j < 8; j++) acc[i][j] = 0ull;

    float4 aR = *(const float4*)Ap;
    float4 bR = *(const float4*)Bp;
    As[(ac+0)*132 + arow] = aR.x; As[(ac+1)*132 + arow] = aR.y;
    As[(ac+2)*132 + arow] = aR.z; As[(ac+3)*132 + arow] = aR.w;
    *(float4*)&Bs[brow*128 + bc4] = bR;
    __syncthreads();

    const int nt = K >> 3;
    int p = 0;
    for (int kt = 0; kt < nt; kt++) {
        const bool has = (kt + 1 < nt);
        if (has) {
            Ap += 8; aR = *(const float4*)Ap;
            Bp += (size_t)8 * ldb; bR = *(const float4*)Bp;
        }
        const float* sa = As + p * (8 * 132);
        const float* sb = Bs + p * (8 * 128);
        #pragma unroll
        for (int kk = 0; kk < 8; kk++) {
            ull a0 = *(const ull*)(sa + kk*132 + r0);
            ull a1 = *(const ull*)(sa + kk*132 + r0 + 2);
            ull a2 = *(const ull*)(sa + kk*132 + r1);
            ull a3 = *(const ull*)(sa + kk*132 + r1 + 2);
            {
                float4 bl4 = *(const float4*)(sb + kk*128 + c0);
                ull b0 = pk2(bl4.x), b1 = pk2(bl4.y), b2 = pk2(bl4.z), b3 = pk2(bl4.w);
                fma2(acc[0][0],a0,b0); fma2(acc[1][0],a1,b0); fma2(acc[2][0],a2,b0); fma2(acc[3][0],a3,b0);
                fma2(acc[0][1],a0,b1); fma2(acc[1][1],a1,b1); fma2(acc[2][1],a2,b1); fma2(acc[3][1],a3,b1);
                fma2(acc[0][2],a0,b2); fma2(acc[1][2],a1,b2); fma2(acc[2][2],a2,b2); fma2(acc[3][2],a3,b2);
                fma2(acc[0][3],a0,b3); fma2(acc[1][3],a1,b3); fma2(acc[2][3],a2,b3); fma2(acc[3][3],a3,b3);
            }
            {
                float4 bh4 = *(const float4*)(sb + kk*128 + c1);
                ull b4 = pk2(bh4.x), b5 = pk2(bh4.y), b6 = pk2(bh4.z), b7 = pk2(bh4.w);
                fma2(acc[0][4],a0,b4); fma2(acc[1][4],a1,b4); fma2(acc[2][4],a2,b4); fma2(acc[3][4],a3,b4);
                fma2(acc[0][5],a0,b5); fma2(acc[1][5],a1,b5); fma2(acc[2][5],a2,b5); fma2(acc[3][5],a3,b5);
                fma2(acc[0][6],a0,b6); fma2(acc[1][6],a1,b6); fma2(acc[2][6],a2,b6); fma2(acc[3][6],a3,b6);
                fma2(acc[0][7],a0,b7); fma2(acc[1][7],a1,b7); fma2(acc[2][7],a2,b7); fma2(acc[3][7],a3,b7);
            }
        }
        if (has) {
            float* sa2 = As + (p^1) * (8 * 132);
            sa2[(ac+0)*132 + arow] = aR.x; sa2[(ac+1)*132 + arow] = aR.y;
            sa2[(ac+2)*132 + arow] = aR.z; sa2[(ac+3)*132 + arow] = aR.w;
            *(float4*)&(Bs + (p^1) * (8*128))[brow*128 + bc4] = bR;
        }
        __syncthreads();
        p ^= 1;
    }

    #pragma unroll
    for (int rp = 0; rp < 4; rp++) {
        const int rloc = (rp < 2) ? (r0 + rp * 2) : (r1 + (rp - 2) * 2);
        float lo[8], hi[8];
        #pragma unroll
        for (int j = 0; j < 8; j++) { float2 t = unpk(acc[rp][j]); lo[j] = t.x; hi[j] = t.y; }
        #pragma unroll
        for (int h2 = 0; h2 < 2; h2++) {
            const int r = bm + rloc + h2;
            #pragma unroll
            for (int g2 = 0; g2 < 2; g2++) {
                const int cb = bn + (g2 ? c1 : c0);
                float v0 = (h2 ? hi[g2*4+0] : lo[g2*4+0]);
                float v1 = (h2 ? hi[g2*4+1] : lo[g2*4+1]);
                float v2 = (h2 ? hi[g2*4+2] : lo[g2*4+2]);
                float v3 = (h2 ? hi[g2*4+3] : lo[g2*4+3]);
                if (EPI == 0) {
                    v0 *= oscale; v1 *= oscale; v2 *= oscale; v3 *= oscale;
                    bf16 h[4], l[4];
                    split(v0,&h[0],&l[0]); split(v1,&h[1],&l[1]);
                    split(v2,&h[2],&l[2]); split(v3,&h[3],&l[3]);
                    uint2 uh, ul;
                    uh.x = (uint32_t)bfbits(h[0]) | ((uint32_t)bfbits(h[1]) << 16);
                    uh.y = (uint32_t)bfbits(h[2]) | ((uint32_t)bfbits(h[3]) << 16);
                    ul.x = (uint32_t)bfbits(l[0]) | ((uint32_t)bfbits(l[1]) << 16);
                    ul.y = (uint32_t)bfbits(l[2]) | ((uint32_t)bfbits(l[3]) << 16);
                    *(uint2*)(Oh + (size_t)r * ldo + cb) = uh;
                    *(uint2*)(Ol + (size_t)r * ldo + cb) = ul;
                } else if (EPI == 2) {
                    float vv[4] = {v0, v1, v2, v3};
                    #pragma unroll
                    for (int j = 0; j < 4; j++) {
                        bf16 hh, ll;
                        split(vv[j], &hh, &ll);
                        Oh[(size_t)(cb + j) * ldo + r] = hh;
                        Ol[(size_t)(cb + j) * ldo + r] = ll;
                    }
                } else if (EPI == 6) {
                    float f0 = fmaxf(v0 + bias[cb+0], 0.f);
                    float f1 = fmaxf(v1 + bias[cb+1], 0.f);
                    float f2 = fmaxf(v2 + bias[cb+2], 0.f);
                    float f3 = fmaxf(v3 + bias[cb+3], 0.f);
                    bf16 h[4], l[4];
                    split(f0,&h[0],&l[0]); split(f1,&h[1],&l[1]);
                    split(f2,&h[2],&l[2]); split(f3,&h[3],&l[3]);
                    uint2 uh, ul;
                    uh.x = (uint32_t)bfbits(h[0]) | ((uint32_t)bfbits(h[1]) << 16);
                    uh.y = (uint32_t)bfbits(h[2]) | ((uint32_t)bfbits(h[3]) << 16);
                    ul.x = (uint32_t)bfbits(l[0]) | ((uint32_t)bfbits(l[1]) << 16);
                    ul.y = (uint32_t)bfbits(l[2]) | ((uint32_t)bfbits(l[3]) << 16);
                    *(uint2*)(Oh + (size_t)r * ldo + cb) = uh;
                    *(uint2*)(Ol + (size_t)r * ldo + cb) = ul;
                    float4 ff; ff.x = f0; ff.y = f1; ff.z = f2; ff.w = f3;
                    *(float4*)(g_ffh_f + (size_t)r * 4096 + cb) = ff;
                } else {  // 4 / 5: fp32 (+bias) + resid
                    const float* rr = resid + (size_t)r * ldc + cb;
                    float4 o;
                    o.x = v0 + rr[0]; o.y = v1 + rr[1];
                    o.z = v2 + rr[2]; o.w = v3 + rr[3];
                    if (EPI == 5) {
                        o.x += bias[cb+0]; o.y += bias[cb+1];
                        o.z += bias[cb+2]; o.w += bias[cb+3];
                    }
                    *(float4*)(Cf + (size_t)r * ldc + cb) = o;
                }
            }
        }
    }
}

// ---------------- hybrid wrappers ----------------
__global__ void __launch_bounds__(256, 2) kt_q(const float* __restrict__ wq) {
    __shared__ __align__(16) uint8_t pool[40960];
    int bx = blockIdx.x, by = blockIdx.y;
    if (bx == 3 || bx == 7)
        score<0>(pool, g_xn_f, wq, 1024, 1024, 1024, by*128, bx*128,
                 nullptr, nullptr, nullptr, 0, g_q_h, g_q_l, 1024, 0.125f);
    else
        tcore<0>(pool, g_xn_h, g_xn_l, 1024, g_wqt_h, g_wqt_l, 1024, 1024,
                 by*128, bx*128, nullptr, 0, g_q_h, g_q_l, 1024, nullptr, nullptr);
}
__global__ void __launch_bounds__(256, 2) kt_k(const float* __restrict__ wk) {
    __shared__ __align__(16) uint8_t pool[40960];
    int bx = blockIdx.x, by = blockIdx.y;
    if (bx == 3 || bx == 7)
        score<0>(pool, g_xn_f, wk, 1024, 1024, 1024, by*128, bx*128,
                 nullptr, nullptr, nullptr, 0, g_k_h, g_k_l, 1024, 1.0f);
    else
        tcore<0>(pool, g_xn_h, g_xn_l, 1024, g_wkt_h, g_wkt_l, 1024, 1024,
                 by*128, bx*128, nullptr, 0, g_k_h, g_k_l, 1024, nullptr, nullptr);
}
__global__ void __launch_bounds__(256, 2) kt_v(const float* __restrict__ wv) {
    __shared__ __align__(16) uint8_t pool[40960];
    int bx = blockIdx.x, by = blockIdx.y;
    if (bx == 3 || bx == 7)
        score<2>(pool, g_xn_f, wv, 1024, 1024, 1024, by*128, bx*128,
                 nullptr, nullptr, nullptr, 0, g_vt_h, g_vt_l, 4096, 1.0f);
    else
        tcore<2>(pool, g_xn_h, g_xn_l, 1024, g_wvt_h, g_wvt_l, 1024, 1024,
                 by*128, bx*128, nullptr, 0, g_vt_h, g_vt_l, 4096, nullptr, nullptr);
}
__global__ void __launch_bounds__(256, 2) kt_wo(const float* __restrict__ wo,
                                                const float* __restrict__ x) {
    __shared__ __align__(16) uint8_t pool[40960];
    int bx = blockIdx.x, by = blockIdx.y;
    if (bx == 3 || bx == 7)
        score<4>(pool, g_ctx_f, wo, 1024, 1024, 1024, by*128, bx*128,
                 nullptr, x, g_x1, 1024, nullptr, nullptr, 0, 1.0f);
    else
        tcore<4>(pool, g_ctx_h, g_ctx_l, 1024, g_wot_h, g_wot_l, 1024, 1024,
                 by*128, bx*128, g_x1, 1024, nullptr, nullptr, 0, nullptr, x);
}
__global__ void __launch_bounds__(256, 2) kt_ffn1(const float* __restrict__ w1,
                                                  const float* __restrict__ b1) {
    __shared__ __align__(16) uint8_t pool[40960];
    int bx = blockIdx.x, by = blockIdx.y;
    if (((bx * 5) & 15) < 5)   // 10 of 32 tiles -> SIMT, interleaved
        score<6>(pool, g_xn_f, w1, 1024, 1024, 4096, by*128, bx*128,
                 b1, nullptr, nullptr, 0, g_ffh_h, g_ffh_l, 4096, 1.0f);
    else
        tcore<6>(pool, g_xn_h, g_xn_l, 1024, g_w1t_h, g_w1t_l, 1024, 1024,
                 by*128, bx*128, nullptr, 0, g_ffh_h, g_ffh_l, 4096, b1, nullptr);
}
__global__ void __launch_bounds__(256, 2) kt_ffn2(const float* __restrict__ w2,
                                                  const float* __restrict__ b2,
                                                  float* __restrict__ out) {
    __shared__ __align__(16) uint8_t pool[40960];
    int bx = blockIdx.x, by = blockIdx.y;
    if (bx == 3 || bx == 7)
        score<5>(pool, g_ffh_f, w2, 4096, 4096, 1024, by*128, bx*128,
                 b2, g_x1, out, 1024, nullptr, nullptr, 0, 1.0f);
    else
        tcore<5>(pool, g_ffh_h, g_ffh_l, 4096, g_w2t_h, g_w2t_l, 4096, 4096,
                 by*128, bx*128, out, 1024, nullptr, nullptr, 0, b2, g_x1);
}

// ---------------- launch ----------------
extern "C" void kernel_launch(void* const* d_in, const int* in_sizes, int n_in,
                              void* d_out, int out_size)
{
    const float* x      = (const float*)d_in[0];
    const int*   mask   = (const int*)  d_in[1];
    const float* wq     = (const float*)d_in[2];
    const float* wk     = (const float*)d_in[3];
    const float* wv     = (const float*)d_in[4];
    const float* wo     = (const float*)d_in[5];
    const float* w1     = (const float*)d_in[6];
    const float* b1     = (const float*)d_in[7];
    const float* w2     = (const float*)d_in[8];
    const float* b2     = (const float*)d_in[9];
    const float* alpha1 = (const float*)d_in[10];
    const float* bias1  = (const float*)d_in[11];
    const float* alpha2 = (const float*)d_in[12];
    const float* bias2  = (const float*)d_in[13];
    float* out = (float*)d_out;

    // weight prep
    k_prep<<<dim3(1024/32, 1024/32), 256>>>(wq, 0, 1024, 1024);
    k_prep<<<dim3(1024/32, 1024/32), 256>>>(wk, 1, 1024, 1024);
    k_prep<<<dim3(1024/32, 1024/32), 256>>>(wv, 2, 1024, 1024);
    k_prep<<<dim3(1024/32, 1024/32), 256>>>(wo, 3, 1024, 1024);
    k_prep<<<dim3(4096/32, 1024/32), 256>>>(w1, 4, 1024, 4096);
    k_prep<<<dim3(1024/32, 4096/32), 256>>>(w2, 5, 4096, 1024);

    // sublayer 1
    k_ln<<<NTOK, 256>>>(x, 0, alpha1, bias1);
    dim3 gP(8, 32);
    kt_q<<<gP, 256>>>(wq);
    kt_k<<<gP, 256>>>(wk);
    kt_v<<<gP, 256>>>(wv);
    kt_attn<<<dim3(16, 32), 256>>>(mask);
    kt_wo<<<gP, 256>>>(wo, x);

    // sublayer 2
    k_ln<<<NTOK, 256>>>(x, 1, alpha2, bias2);
    dim3 gF1(32, 32);
    kt_ffn1<<<gF1, 256>>>(w1, b1);
    dim3 gF2(8, 32);
    kt_ffn2<<<gF2, 256>>>(w2, b2, out);
}

// round 9
// speedup vs baseline: 1.6396x; 1.6396x over previous
#include <cuda_runtime.h>
#include <cuda_bf16.h>
#include <math.h>
#include <stdint.h>

#define DMODEL 1024
#define DFF 4096
#define SEQ 2048
#define NTOK 4096
#define LN_EPS 1e-5f
typedef __nv_bfloat16 bf16;

// ---------------- device-global scratch ----------------
__device__ bf16 g_wqt_h[1u<<20], g_wqt_l[1u<<20];   // [N,K] K-major (wq pre-scaled 0.125)
__device__ bf16 g_wkt_h[1u<<20], g_wkt_l[1u<<20];
__device__ bf16 g_wvt_h[1u<<20], g_wvt_l[1u<<20];
__device__ bf16 g_wot_h[1u<<20], g_wot_l[1u<<20];
__device__ bf16 g_w1t_h[1u<<22], g_w1t_l[1u<<22];   // [4096,1024]
__device__ bf16 g_w2t_h[1u<<22], g_w2t_l[1u<<22];   // [1024,4096]
__device__ bf16 g_xn_h [1u<<22], g_xn_l [1u<<22];
__device__ bf16 g_q_h  [1u<<22], g_q_l  [1u<<22];
__device__ bf16 g_k_h  [1u<<22], g_k_l  [1u<<22];
__device__ bf16 g_vt_h [1u<<22], g_vt_l [1u<<22];   // [1024 dk, 4096 tok]
__device__ bf16 g_ctx_h[1u<<22], g_ctx_l[1u<<22];
__device__ bf16 g_ffh_h[1u<<24], g_ffh_l[1u<<24];   // [4096,4096]
__device__ float g_x1[1u<<22];

// ---------------- helpers ----------------
__device__ __forceinline__ void mma16816(float* d, const uint32_t* a, const uint32_t* b) {
    asm volatile(
        "mma.sync.aligned.m16n8k16.row.col.f32.bf16.bf16.f32 "
        "{%0,%1,%2,%3}, {%4,%5,%6,%7}, {%8,%9}, {%0,%1,%2,%3};"
        : "+f"(d[0]), "+f"(d[1]), "+f"(d[2]), "+f"(d[3])
        : "r"(a[0]), "r"(a[1]), "r"(a[2]), "r"(a[3]), "r"(b[0]), "r"(b[1]));
}
__device__ __forceinline__ uint16_t bfbits(bf16 v) { return __bfloat16_as_ushort(v); }
__device__ __forceinline__ void split(float f, bf16* h, bf16* l) {
    bf16 hh = __float2bfloat16(f);
    *h = hh; *l = __float2bfloat16(f - __bfloat162float(hh));
}
__device__ __forceinline__ float warpSum(float v) {
    #pragma unroll
    for (int o = 16; o > 0; o >>= 1) v += __shfl_down_sync(0xffffffffu, v, o);
    return v;
}
__device__ __forceinline__ float blockSum(float v) {
    __shared__ float sh[8];
    int l = threadIdx.x & 31, w = threadIdx.x >> 5;
    v = warpSum(v);
    if (l == 0) sh[w] = v;
    __syncthreads();
    if (w == 0) { float t = (l < 8) ? sh[l] : 0.f; t = warpSum(t); if (l == 0) sh[0] = t; }
    __syncthreads();
    float r = sh[0]; __syncthreads();
    return r;
}

// ---------------- weight prep: ONE launch for all six weights ----------------
// tiles: [0,4096) wq/wk/wv/wo (1024 each), [4096,8192) w1, [8192,12288) w2
__global__ void __launch_bounds__(256) k_prep_all(
    const float* __restrict__ wq, const float* __restrict__ wk,
    const float* __restrict__ wv, const float* __restrict__ wo,
    const float* __restrict__ w1, const float* __restrict__ w2)
{
    int t = blockIdx.x;
    const float* w; bf16 *th, *tl;
    int K, N, local;
    float scale = 1.0f;
    if (t < 4096) {
        int seg = t >> 10; local = t & 1023;
        K = 1024; N = 1024;
        switch (seg) {
            case 0: w = wq; th = g_wqt_h; tl = g_wqt_l; scale = 0.125f; break;
            case 1: w = wk; th = g_wkt_h; tl = g_wkt_l; break;
            case 2: w = wv; th = g_wvt_h; tl = g_wvt_l; break;
            default: w = wo; th = g_wot_h; tl = g_wot_l; break;
        }
    } else if (t < 8192) {
        local = t - 4096; w = w1; th = g_w1t_h; tl = g_w1t_l; K = 1024; N = 4096;
    } else {
        local = t - 8192; w = w2; th = g_w2t_h; tl = g_w2t_l; K = 4096; N = 1024;
    }
    const int xt = N >> 5;
    const int n0 = (local % xt) * 32, k0 = (local / xt) * 32;

    __shared__ float ts[32][33];
    int tx = threadIdx.x & 31, ty = threadIdx.x >> 5;
    #pragma unroll
    for (int i = 0; i < 4; i++)
        ts[ty + 8*i][tx] = w[(size_t)(k0 + ty + 8*i) * N + n0 + tx];
    __syncthreads();
    #pragma unroll
    for (int i = 0; i < 4; i++) {
        int n = n0 + ty + 8*i, k = k0 + tx;
        split(ts[tx][ty + 8*i] * scale, &th[(size_t)n * K + k], &tl[(size_t)n * K + k]);
    }
}

// ---------------- LayerNorm -> bf16 hi/lo ----------------
__global__ void __launch_bounds__(256) k_ln(const float* __restrict__ xin, int use_x1,
                                            const float* __restrict__ ap,
                                            const float* __restrict__ bp)
{
    const float* src = use_x1 ? g_x1 : xin;
    int row = blockIdx.x, t = threadIdx.x;
    const float* xr = src + (size_t)row * DMODEL;
    float v[4], s = 0.f, sq = 0.f;
    #pragma unroll
    for (int i = 0; i < 4; i++) { v[i] = xr[t + 256*i]; s += v[i]; sq += v[i]*v[i]; }
    s = blockSum(s); sq = blockSum(sq);
    float mean = s * (1.0f / DMODEL);
    float var = fmaxf((sq - (float)DMODEL * mean * mean) * (1.0f / (DMODEL - 1)), 0.f);
    float sc = ap[0] / (sqrtf(var) + LN_EPS);
    float bi = bp[0];
    #pragma unroll
    for (int i = 0; i < 4; i++) {
        size_t o = (size_t)row * DMODEL + t + 256*i;
        split((v[i] - mean) * sc + bi, &g_xn_h[o], &g_xn_l[o]);
    }
}

// ---------------------------------------------------------------------------
// Fused flash attention (identical to R7)
// ---------------------------------------------------------------------------
__global__ void __launch_bounds__(256) kt_attn(const int* __restrict__ mask)
{
    const int z = blockIdx.y, b = z >> 4, h = z & 15;
    const int q0 = blockIdx.x * 128;
    const int tid = threadIdx.x, wid = tid >> 5, lane = tid & 31;
    const int g = lane >> 2, t4 = lane & 3;

    __shared__ __align__(16) uint16_t sKh[64*72], sKl[64*72];
    __shared__ __align__(16) uint16_t sVh[64*72], sVl[64*72];
    __shared__ int s_mask[SEQ];

    for (int i = tid; i < SEQ/4; i += 256)
        *(int4*)&s_mask[i*4] = *(const int4*)&mask[b*SEQ + i*4];

    uint32_t qh[4][4], ql[4][4];
    {
        const uint32_t* Q32h = (const uint32_t*)g_q_h;
        const uint32_t* Q32l = (const uint32_t*)g_q_l;
        size_t r0 = ((size_t)(b*SEQ + q0 + wid*16 + g)) * 512 + h*32;
        size_t r8 = r0 + 8*512;
        #pragma unroll
        for (int s = 0; s < 4; s++) {
            qh[s][0] = Q32h[r0 + s*8 + t4];
            qh[s][1] = Q32h[r8 + s*8 + t4];
            qh[s][2] = Q32h[r0 + s*8 + 4 + t4];
            qh[s][3] = Q32h[r8 + s*8 + 4 + t4];
            ql[s][0] = Q32l[r0 + s*8 + t4];
            ql[s][1] = Q32l[r8 + s*8 + t4];
            ql[s][2] = Q32l[r0 + s*8 + 4 + t4];
            ql[s][3] = Q32l[r8 + s*8 + 4 + t4];
        }
    }

    float O[8][4];
    #pragma unroll
    for (int i = 0; i < 8; i++)
        #pragma unroll
        for (int j = 0; j < 4; j++) O[i][j] = 0.f;
    float m0 = -INFINITY, m1 = -INFINITY, l0 = 0.f, l1 = 0.f;

    const int krow = tid >> 2, kcb = (tid & 3) * 16;
    const uint32_t* K32h = (const uint32_t*)sKh;
    const uint32_t* K32l = (const uint32_t*)sKl;
    const uint32_t* V32h = (const uint32_t*)sVh;
    const uint32_t* V32l = (const uint32_t*)sVl;

    for (int kt = 0; kt < SEQ/64; kt++) {
        __syncthreads();
        {
            size_t gk = ((size_t)(b*SEQ + kt*64 + krow)) * 1024 + h*64 + kcb;
            *(uint4*)&sKh[krow*72 + kcb]     = *(const uint4*)&g_k_h[gk];
            *(uint4*)&sKh[krow*72 + kcb + 8] = *(const uint4*)&g_k_h[gk + 8];
            *(uint4*)&sKl[krow*72 + kcb]     = *(const uint4*)&g_k_l[gk];
            *(uint4*)&sKl[krow*72 + kcb + 8] = *(const uint4*)&g_k_l[gk + 8];
            size_t gv = ((size_t)(h*64 + krow)) * 4096 + b*SEQ + kt*64 + kcb;
            *(uint4*)&sVh[krow*72 + kcb]     = *(const uint4*)&g_vt_h[gv];
            *(uint4*)&sVh[krow*72 + kcb + 8] = *(const uint4*)&g_vt_h[gv + 8];
            *(uint4*)&sVl[krow*72 + kcb]     = *(const uint4*)&g_vt_l[gv];
            *(uint4*)&sVl[krow*72 + kcb + 8] = *(const uint4*)&g_vt_l[gv + 8];
        }
        __syncthreads();

        float s[8][4];
        #pragma unroll
        for (int nt = 0; nt < 8; nt++) {
            s[nt][0] = s[nt][1] = s[nt][2] = s[nt][3] = 0.f;
            const int nr = (nt*8 + g) * 36;
            #pragma unroll
            for (int ks = 0; ks < 4; ks++) {
                uint32_t bh[2] = { K32h[nr + ks*8 + t4], K32h[nr + ks*8 + 4 + t4] };
                uint32_t bl[2] = { K32l[nr + ks*8 + t4], K32l[nr + ks*8 + 4 + t4] };
                mma16816(s[nt], qh[ks], bh);
                mma16816(s[nt], qh[ks], bl);
                mma16816(s[nt], ql[ks], bh);
            }
        }
        #pragma unroll
        for (int nt = 0; nt < 8; nt++) {
            const int c = kt*64 + nt*8 + 2*t4;
            if (s_mask[c]   == 0) { s[nt][0] = -1e9f; s[nt][2] = -1e9f; }
            if (s_mask[c+1] == 0) { s[nt][1] = -1e9f; s[nt][3] = -1e9f; }
        }
        float mx0 = -INFINITY, mx1 = -INFINITY;
        #pragma unroll
        for (int nt = 0; nt < 8; nt++) {
            mx0 = fmaxf(mx0, fmaxf(s[nt][0], s[nt][1]));
            mx1 = fmaxf(mx1, fmaxf(s[nt][2], s[nt][3]));
        }
        mx0 = fmaxf(mx0, __shfl_xor_sync(0xffffffffu, mx0, 1));
        mx0 = fmaxf(mx0, __shfl_xor_sync(0xffffffffu, mx0, 2));
        mx1 = fmaxf(mx1, __shfl_xor_sync(0xffffffffu, mx1, 1));
        mx1 = fmaxf(mx1, __shfl_xor_sync(0xffffffffu, mx1, 2));
        float nm0 = fmaxf(m0, mx0), nm1 = fmaxf(m1, mx1);
        float a0 = __expf(m0 - nm0), a1 = __expf(m1 - nm1);
        m0 = nm0; m1 = nm1;
        float ps0 = 0.f, ps1 = 0.f;
        #pragma unroll
        for (int nt = 0; nt < 8; nt++) {
            s[nt][0] = __expf(s[nt][0] - nm0);
            s[nt][1] = __expf(s[nt][1] - nm0);
            s[nt][2] = __expf(s[nt][2] - nm1);
            s[nt][3] = __expf(s[nt][3] - nm1);
            ps0 += s[nt][0] + s[nt][1];
            ps1 += s[nt][2] + s[nt][3];
        }
        ps0 += __shfl_xor_sync(0xffffffffu, ps0, 1);
        ps0 += __shfl_xor_sync(0xffffffffu, ps0, 2);
        ps1 += __shfl_xor_sync(0xffffffffu, ps1, 1);
        ps1 += __shfl_xor_sync(0xffffffffu, ps1, 2);
        l0 = l0 * a0 + ps0;
        l1 = l1 * a1 + ps1;
        #pragma unroll
        for (int nt = 0; nt < 8; nt++) {
            O[nt][0] *= a0; O[nt][1] *= a0;
            O[nt][2] *= a1; O[nt][3] *= a1;
        }
        uint32_t pH[4][4], pL[4][4];
        #pragma unroll
        for (int ks = 0; ks < 4; ks++) {
            #pragma unroll
            for (int half = 0; half < 2; half++) {
                const int nt = 2*ks + half;
                bf16 h0 = __float2bfloat16(s[nt][0]);
                bf16 h1 = __float2bfloat16(s[nt][1]);
                bf16 h2 = __float2bfloat16(s[nt][2]);
                bf16 h3 = __float2bfloat16(s[nt][3]);
                pH[ks][2*half]   = (uint32_t)bfbits(h0) | ((uint32_t)bfbits(h1) << 16);
                pH[ks][2*half+1] = (uint32_t)bfbits(h2) | ((uint32_t)bfbits(h3) << 16);
                bf16 e0 = __float2bfloat16(s[nt][0] - __bfloat162float(h0));
                bf16 e1 = __float2bfloat16(s[nt][1] - __bfloat162float(h1));
                bf16 e2 = __float2bfloat16(s[nt][2] - __bfloat162float(h2));
                bf16 e3 = __float2bfloat16(s[nt][3] - __bfloat162float(h3));
                pL[ks][2*half]   = (uint32_t)bfbits(e0) | ((uint32_t)bfbits(e1) << 16);
                pL[ks][2*half+1] = (uint32_t)bfbits(e2) | ((uint32_t)bfbits(e3) << 16);
            }
        }
        #pragma unroll
        for (int nt = 0; nt < 8; nt++) {
            const int nr = (nt*8 + g) * 36;
            #pragma unroll
            for (int ks = 0; ks < 4; ks++) {
                uint32_t bh[2] = { V32h[nr + ks*8 + t4], V32h[nr + ks*8 + 4 + t4] };
                uint32_t bl[2] = { V32l[nr + ks*8 + t4], V32l[nr + ks*8 + 4 + t4] };
                mma16816(O[nt], pH[ks], bh);
                mma16816(O[nt], pH[ks], bl);
                mma16816(O[nt], pL[ks], bh);
            }
        }
    }

    const float il0 = 1.0f / l0, il1 = 1.0f / l1;
    const size_t row0 = (size_t)(b*SEQ + q0 + wid*16 + g);
    const size_t row8 = row0 + 8;
    #pragma unroll
    for (int nt = 0; nt < 8; nt++) {
        const int col = h*64 + nt*8 + 2*t4;
        bf16 h0, l0b, h1, l1b;
        split(O[nt][0] * il0, &h0, &l0b);
        split(O[nt][1] * il0, &h1, &l1b);
        *(uint32_t*)(g_ctx_h + row0*1024 + col) =
            (uint32_t)bfbits(h0) | ((uint32_t)bfbits(h1) << 16);
        *(uint32_t*)(g_ctx_l + row0*1024 + col) =
            (uint32_t)bfbits(l0b) | ((uint32_t)bfbits(l1b) << 16);
        split(O[nt][2] * il1, &h0, &l0b);
        split(O[nt][3] * il1, &h1, &l1b);
        *(uint32_t*)(g_ctx_h + row8*1024 + col) =
            (uint32_t)bfbits(h0) | ((uint32_t)bfbits(h1) << 16);
        *(uint32_t*)(g_ctx_l + row8*1024 + col) =
            (uint32_t)bfbits(l0b) | ((uint32_t)bfbits(l1b) << 16);
    }
}

// ---------------------------------------------------------------------------
// mma.sync GEMM core (identical to R7): 128(M) x NT(N), K-chunks of 32.
// EPI: 0 pair-out | 1 bias+relu pair-out | 2 pair-out transposed
//      4 fp32+resid | 5 fp32+bias+resid
// ---------------------------------------------------------------------------
template<int NT, int EPI>
__device__ __forceinline__ void tcore(
    const bf16* __restrict__ Ah, const bf16* __restrict__ Al, int lda,
    const bf16* __restrict__ Bh, const bf16* __restrict__ Bl, int ldb,
    int K, int bm, int bn,
    float* __restrict__ Cf, int ldc,
    bf16* __restrict__ Oh, bf16* __restrict__ Ol, int ldo,
    const float* __restrict__ bias, const float* __restrict__ resid)
{
    constexpr int RS   = 40;
    constexpr int WN   = NT / 2;
    constexpr int NTIL = WN / 8;
    __shared__ __align__(16) uint16_t sAh[128*RS], sAl[128*RS];
    __shared__ __align__(16) uint16_t sBh[NT*RS],  sBl[NT*RS];

    const int tid = threadIdx.x, wid = tid >> 5, lane = tid & 31;
    const int wm = wid & 3, wn = wid >> 2;
    const int g = lane >> 2, t4 = lane & 3;

    const int ar = tid >> 1, akq = (tid & 1) * 16;
    const int br128 = tid >> 1, bkq128 = (tid & 1) * 16;
    const int br64 = tid >> 2, bkq64 = (tid & 3) * 8;

    float acc[2][NTIL][4];
    #pragma unroll
    for (int i = 0; i < 2; i++)
        #pragma unroll
        for (int j = 0; j < NTIL; j++)
            #pragma unroll
            for (int e = 0; e < 4; e++) acc[i][j][e] = 0.f;

    uint4 pAh[2], pAl[2], pBh[2], pBl[2];
    auto prefetch = [&](int k0) {
        const bf16* a_h = Ah + (size_t)(bm + ar) * lda + k0 + akq;
        const bf16* a_l = Al + (size_t)(bm + ar) * lda + k0 + akq;
        pAh[0] = *(const uint4*)a_h;       pAh[1] = *(const uint4*)(a_h + 8);
        pAl[0] = *(const uint4*)a_l;       pAl[1] = *(const uint4*)(a_l + 8);
        if (NT == 128) {
            const bf16* b_h = Bh + (size_t)(bn + br128) * ldb + k0 + bkq128;
            const bf16* b_l = Bl + (size_t)(bn + br128) * ldb + k0 + bkq128;
            pBh[0] = *(const uint4*)b_h;   pBh[1] = *(const uint4*)(b_h + 8);
            pBl[0] = *(const uint4*)b_l;   pBl[1] = *(const uint4*)(b_l + 8);
        } else {
            pBh[0] = *(const uint4*)(Bh + (size_t)(bn + br64) * ldb + k0 + bkq64);
            pBl[0] = *(const uint4*)(Bl + (size_t)(bn + br64) * ldb + k0 + bkq64);
        }
    };
    auto store_smem = [&]() {
        *(uint4*)&sAh[ar*RS + akq]     = pAh[0];
        *(uint4*)&sAh[ar*RS + akq + 8] = pAh[1];
        *(uint4*)&sAl[ar*RS + akq]     = pAl[0];
        *(uint4*)&sAl[ar*RS + akq + 8] = pAl[1];
        if (NT == 128) {
            *(uint4*)&sBh[br128*RS + bkq128]     = pBh[0];
            *(uint4*)&sBh[br128*RS + bkq128 + 8] = pBh[1];
            *(uint4*)&sBl[br128*RS + bkq128]     = pBl[0];
            *(uint4*)&sBl[br128*RS + bkq128 + 8] = pBl[1];
        } else {
            *(uint4*)&sBh[br64*RS + bkq64] = pBh[0];
            *(uint4*)&sBl[br64*RS + bkq64] = pBl[0];
        }
    };

    const uint32_t* A32h = (const uint32_t*)sAh;
    const uint32_t* A32l = (const uint32_t*)sAl;
    const uint32_t* B32h = (const uint32_t*)sBh;
    const uint32_t* B32l = (const uint32_t*)sBl;
    const int RS2 = RS / 2;

    const int nch = K >> 5;
    prefetch(0);
    for (int c = 0; c < nch; c++) {
        __syncthreads();
        store_smem();
        __syncthreads();
        if (c + 1 < nch) prefetch((c + 1) << 5);

        #pragma unroll
        for (int kh = 0; kh < 2; kh++) {
            const int ko = kh * 8;
            uint32_t aH[2][4], aL[2][4];
            #pragma unroll
            for (int mt = 0; mt < 2; mt++) {
                const int r = wm*32 + mt*16 + g;
                aH[mt][0] = A32h[r*RS2 + ko + t4];
                aH[mt][1] = A32h[(r+8)*RS2 + ko + t4];
                aH[mt][2] = A32h[r*RS2 + ko + 4 + t4];
                aH[mt][3] = A32h[(r+8)*RS2 + ko + 4 + t4];
                aL[mt][0] = A32l[r*RS2 + ko + t4];
                aL[mt][1] = A32l[(r+8)*RS2 + ko + t4];
                aL[mt][2] = A32l[r*RS2 + ko + 4 + t4];
                aL[mt][3] = A32l[(r+8)*RS2 + ko + 4 + t4];
            }
            #pragma unroll
            for (int nt = 0; nt < NTIL; nt++) {
                const int nr = wn*WN + nt*8 + g;
                uint32_t bH[2], bL[2];
                bH[0] = B32h[nr*RS2 + ko + t4];
                bH[1] = B32h[nr*RS2 + ko + 4 + t4];
                bL[0] = B32l[nr*RS2 + ko + t4];
                bL[1] = B32l[nr*RS2 + ko + 4 + t4];
                #pragma unroll
                for (int mt = 0; mt < 2; mt++) {
                    mma16816(acc[mt][nt], aH[mt], bH);
                    mma16816(acc[mt][nt], aH[mt], bL);
                    mma16816(acc[mt][nt], aL[mt], bH);
                }
            }
        }
    }

    auto wr = [&](int row, int col, float v0, float v1) {
        if (EPI == 0 || EPI == 1) {
            if (EPI == 1) {
                v0 = fmaxf(v0 + bias[col], 0.f);
                v1 = fmaxf(v1 + bias[col + 1], 0.f);
            }
            bf16 h0, l0, h1, l1;
            split(v0, &h0, &l0); split(v1, &h1, &l1);
            *(uint32_t*)(Oh + (size_t)row * ldo + col) =
                (uint32_t)bfbits(h0) | ((uint32_t)bfbits(h1) << 16);
            *(uint32_t*)(Ol + (size_t)row * ldo + col) =
                (uint32_t)bfbits(l0) | ((uint32_t)bfbits(l1) << 16);
        } else if (EPI == 2) {
            bf16 h0, l0, h1, l1;
            split(v0, &h0, &l0); split(v1, &h1, &l1);
            Oh[(size_t)col * ldo + row] = h0;
            Ol[(size_t)col * ldo + row] = l0;
            Oh[(size_t)(col + 1) * ldo + row] = h1;
            Ol[(size_t)(col + 1) * ldo + row] = l1;
        } else {
            const float* rr = resid + (size_t)row * ldc + col;
            float2 o;
            o.x = v0 + rr[0]; o.y = v1 + rr[1];
            if (EPI == 5) { o.x += bias[col]; o.y += bias[col + 1]; }
            *(float2*)(Cf + (size_t)row * ldc + col) = o;
        }
    };
    #pragma unroll
    for (int mt = 0; mt < 2; mt++) {
        #pragma unroll
        for (int nt = 0; nt < NTIL; nt++) {
            const int row = bm + wm*32 + mt*16 + g;
            const int col = bn + wn*WN + nt*8 + 2*t4;
            wr(row,     col, acc[mt][nt][0], acc[mt][nt][1]);
            wr(row + 8, col, acc[mt][nt][2], acc[mt][nt][3]);
        }
    }
}

// ---------------- wrappers ----------------
// Q/K/V merged into one launch: z = 0 (Q), 1 (K), 2 (V transposed out)
__global__ void __launch_bounds__(256) kt_qkv() {
    const int bm = blockIdx.y * 128, bn = blockIdx.x * 128;
    if (blockIdx.z == 0)
        tcore<128,0>(g_xn_h, g_xn_l, 1024, g_wqt_h, g_wqt_l, 1024, 1024,
                     bm, bn, nullptr, 0, g_q_h, g_q_l, 1024, nullptr, nullptr);
    else if (blockIdx.z == 1)
        tcore<128,0>(g_xn_h, g_xn_l, 1024, g_wkt_h, g_wkt_l, 1024, 1024,
                     bm, bn, nullptr, 0, g_k_h, g_k_l, 1024, nullptr, nullptr);
    else
        tcore<128,2>(g_xn_h, g_xn_l, 1024, g_wvt_h, g_wvt_l, 1024, 1024,
                     bm, bn, nullptr, 0, g_vt_h, g_vt_l, 4096, nullptr, nullptr);
}
__global__ void __launch_bounds__(256) kt_wo(const float* __restrict__ x) {
    tcore<128,4>(g_ctx_h, g_ctx_l, 1024, g_wot_h, g_wot_l, 1024, 1024,
                 blockIdx.y*128, blockIdx.x*128,
                 g_x1, 1024, nullptr, nullptr, 0, nullptr, x);
}
__global__ void __launch_bounds__(256) kt_ffn1(const float* __restrict__ b1) {
    tcore<128,1>(g_xn_h, g_xn_l, 1024, g_w1t_h, g_w1t_l, 1024, 1024,
                 blockIdx.y*128, blockIdx.x*128,
                 nullptr, 0, g_ffh_h, g_ffh_l, 4096, b1, nullptr);
}
__global__ void __launch_bounds__(256) kt_ffn2(const float* __restrict__ b2,
                                               float* __restrict__ out) {
    tcore<128,5>(g_ffh_h, g_ffh_l, 4096, g_w2t_h, g_w2t_l, 4096, 4096,
                 blockIdx.y*128, blockIdx.x*128,
                 out, 1024, nullptr, nullptr, 0, b2, g_x1);
}

// ---------------- launch ----------------
extern "C" void kernel_launch(void* const* d_in, const int* in_sizes, int n_in,
                              void* d_out, int out_size)
{
    const float* x      = (const float*)d_in[0];
    const int*   mask   = (const int*)  d_in[1];
    const float* wq     = (const float*)d_in[2];
    const float* wk     = (const float*)d_in[3];
    const float* wv     = (const float*)d_in[4];
    const float* wo     = (const float*)d_in[5];
    const float* w1     = (const float*)d_in[6];
    const float* b1     = (const float*)d_in[7];
    const float* w2     = (const float*)d_in[8];
    const float* b2     = (const float*)d_in[9];
    const float* alpha1 = (const float*)d_in[10];
    const float* bias1  = (const float*)d_in[11];
    const float* alpha2 = (const float*)d_in[12];
    const float* bias2  = (const float*)d_in[13];
    float* out = (float*)d_out;

    // weight prep — single launch
    k_prep_all<<<12288, 256>>>(wq, wk, wv, wo, w1, w2);

    // sublayer 1
    k_ln<<<NTOK, 256>>>(x, 0, alpha1, bias1);
    kt_qkv<<<dim3(8, 32, 3), 256>>>();
    kt_attn<<<dim3(16, 32), 256>>>(mask);
    kt_wo<<<dim3(8, 32), 256>>>(x);

    // sublayer 2
    k_ln<<<NTOK, 256>>>(x, 1, alpha2, bias2);
    kt_ffn1<<<dim3(32, 32), 256>>>(b1);
    kt_ffn2<<<dim3(8, 32), 256>>>(b2, out);
}